// round 1
// baseline (speedup 1.0000x reference)
#include <cuda_runtime.h>
#include <cstdint>
#include <math.h>

#define SEQ 4096
#define H 2048
#define IN_DIM 2048
#define G3 6144

// ---------------- scratch (static device allocations are allowed) ----------
__device__ float g_igates[(size_t)SEQ * G3];   // ~100.7 MB
__device__ unsigned int g_bar;

__global__ void init_bar_kernel() { g_bar = 0u; }

// ---------------- Kernel 1: igates = xs @ Wi^T + bi ------------------------
// A = xs [4096,2048] row-major, B = Wi [6144,2048] row-major (both K-contiguous)
// C[t][j] = sum_k A[t][k]*B[j][k] + bi[j]
#define GBM 128
#define GBN 128
#define GBK 16

__global__ __launch_bounds__(256) void igates_gemm(
    const float* __restrict__ A,
    const float* __restrict__ B,
    const float* __restrict__ bias)
{
    __shared__ float As[GBK][GBM + 1];
    __shared__ float Bs[GBK][GBN + 1];

    const int bm = blockIdx.y * GBM;   // t tile
    const int bn = blockIdx.x * GBN;   // j tile
    const int tid = threadIdx.x;
    const int tx = tid & 15;           // 0..15  -> 8 cols each
    const int ty = tid >> 4;           // 0..15  -> 8 rows each
    const int lr = tid >> 2;           // 0..63  loader row
    const int lc = tid & 3;            // 0..3   loader float4 col

    float acc[8][8];
    #pragma unroll
    for (int i = 0; i < 8; i++)
        #pragma unroll
        for (int j = 0; j < 8; j++) acc[i][j] = 0.f;

    for (int k0 = 0; k0 < IN_DIM; k0 += GBK) {
        #pragma unroll
        for (int s = 0; s < 2; s++) {
            const int row = lr + 64 * s;
            float4 va = *(const float4*)(A + (size_t)(bm + row) * IN_DIM + k0 + 4 * lc);
            As[4*lc+0][row] = va.x; As[4*lc+1][row] = va.y;
            As[4*lc+2][row] = va.z; As[4*lc+3][row] = va.w;
            float4 vb = *(const float4*)(B + (size_t)(bn + row) * IN_DIM + k0 + 4 * lc);
            Bs[4*lc+0][row] = vb.x; Bs[4*lc+1][row] = vb.y;
            Bs[4*lc+2][row] = vb.z; Bs[4*lc+3][row] = vb.w;
        }
        __syncthreads();

        #pragma unroll
        for (int k = 0; k < GBK; k++) {
            float a[8], b[8];
            #pragma unroll
            for (int i = 0; i < 8; i++) a[i] = As[k][ty * 8 + i];
            #pragma unroll
            for (int j = 0; j < 8; j++) b[j] = Bs[k][tx * 8 + j];
            #pragma unroll
            for (int i = 0; i < 8; i++)
                #pragma unroll
                for (int j = 0; j < 8; j++) acc[i][j] += a[i] * b[j];
        }
        __syncthreads();
    }

    // epilogue: add bias, vectorized stores
    #pragma unroll
    for (int i = 0; i < 8; i++) {
        const int row = bm + ty * 8 + i;
        const int col = bn + tx * 8;
        float4 o0, o1;
        o0.x = acc[i][0] + bias[col + 0];
        o0.y = acc[i][1] + bias[col + 1];
        o0.z = acc[i][2] + bias[col + 2];
        o0.w = acc[i][3] + bias[col + 3];
        o1.x = acc[i][4] + bias[col + 4];
        o1.y = acc[i][5] + bias[col + 5];
        o1.z = acc[i][6] + bias[col + 6];
        o1.w = acc[i][7] + bias[col + 7];
        float* cp = g_igates + (size_t)row * G3 + col;
        *(float4*)(cp + 0) = o0;
        *(float4*)(cp + 4) = o1;
    }
}

// ---------------- Kernel 2: persistent GRU recurrence ----------------------
// 128 CTAs (1/SM, all co-resident), each owns 16 hidden indices => 48 Wh rows.
// 24 rows cached in SMEM (fp32), 24 streamed from L2 each step.
// h flows through `out` rows (L2) with __stcg/__ldcg; one grid barrier / step.
#define NCTA 128
#define PER 16
#define NROWS 48
#define CACHED 24
#define RTH 256

__global__ __launch_bounds__(RTH, 1) void gru_recur(
    const float* __restrict__ init_state,
    const float* __restrict__ Wh,
    const float* __restrict__ bn,
    float* __restrict__ out)
{
    extern __shared__ float smem[];
    float* h_s = smem;                      // H floats
    float* wc  = smem + H;                  // CACHED * H floats
    float* red = smem + H + CACHED * H;     // NROWS floats

    const int tid  = threadIdx.x;
    const int lane = tid & 31;
    const int wid  = tid >> 5;
    const int base = blockIdx.x * PER;

    // prologue: cache first CACHED rows of this CTA's Wh slice
    for (int r = 0; r < CACHED; r++) {
        const int gate = r >> 4, i = r & 15;
        const float4* src = (const float4*)(Wh + (size_t)(gate * H + base + i) * H);
        float4* dst = (float4*)(wc + r * H);
        for (int v = tid; v < H / 4; v += RTH) dst[v] = src[v];
    }

    float bnv = 0.f, lastv = 0.f;
    if (tid < PER) bnv = bn[base + tid];

    for (int t = 0; t < SEQ; t++) {
        // ---- load h_{t-1} into SMEM (L2-coherent loads) ----
        const float4* hsrc = (t == 0) ? (const float4*)init_state
                                      : (const float4*)(out + (size_t)(t - 1) * H);
        for (int v = tid; v < H / 4; v += RTH)
            ((float4*)h_s)[v] = __ldcg(hsrc + v);
        __syncthreads();

        // ---- 48 dot products: warp per row, 6 rows per warp ----
        for (int rr = wid; rr < NROWS; rr += RTH / 32) {
            const int gate = rr >> 4, i = rr & 15;
            const float4* wp = (rr < CACHED)
                ? (const float4*)(wc + rr * H)
                : (const float4*)(Wh + (size_t)(gate * H + base + i) * H);
            float sx = 0.f, sy = 0.f, sz = 0.f, sw = 0.f;
            #pragma unroll
            for (int j = 0; j < H / 128; j++) {   // 16 iters
                float4 w  = wp[j * 32 + lane];
                float4 hv = ((const float4*)h_s)[j * 32 + lane];
                sx += w.x * hv.x; sy += w.y * hv.y;
                sz += w.z * hv.z; sw += w.w * hv.w;
            }
            float s = (sx + sy) + (sz + sw);
            #pragma unroll
            for (int o = 16; o; o >>= 1) s += __shfl_xor_sync(0xffffffffu, s, o);
            if (lane == 0) red[rr] = s;
        }
        __syncthreads();

        // ---- gate math + write h_t ----
        if (tid < PER) {
            const int idx = base + tid;
            const float hr = red[tid], hz = red[PER + tid], hn = red[2 * PER + tid];
            const float* ig = g_igates + (size_t)t * G3;
            const float gr = ig[idx], gz = ig[H + idx], gn = ig[2 * H + idx];
            const float reset  = 1.f / (1.f + expf(-(gr + hr)));
            const float update = 1.f / (1.f + expf(-(gz + hz)));
            const float nv = tanhf(gn + reset * (hn + bnv));
            const float hp = h_s[idx];
            const float hnext = (1.f - update) * nv + update * hp;
            __stcg(out + (size_t)t * H + idx, hnext);
            lastv = hnext;
        }
        // release: make h_t visible device-wide before signaling
        __threadfence();
        __syncthreads();

        // ---- grid barrier (monotonic counter; reset per launch) ----
        if (tid == 0) {
            atomicAdd(&g_bar, 1u);
            const unsigned target = (unsigned)(t + 1) * NCTA;
            while (*((volatile unsigned int*)&g_bar) < target) { }
            __threadfence();   // acquire
        }
        __syncthreads();
    }

    // last_state = all_states[SEQ-1]
    if (tid < PER) out[(size_t)SEQ * H + base + tid] = lastv;
}

// ---------------- launch -----------------------------------------------------
extern "C" void kernel_launch(void* const* d_in, const int* in_sizes, int n_in,
                              void* d_out, int out_size)
{
    const float* xs         = (const float*)d_in[0];   // [4096,2048]
    const float* init_state = (const float*)d_in[1];   // [2048]
    const float* Wi         = (const float*)d_in[2];   // [6144,2048]
    const float* Wh         = (const float*)d_in[3];   // [6144,2048]
    const float* bi         = (const float*)d_in[4];   // [6144]
    const float* bn         = (const float*)d_in[5];   // [2048]
    float* out = (float*)d_out;                        // [4096*2048 + 2048]

    init_bar_kernel<<<1, 1>>>();

    dim3 ggrid(G3 / GBN, SEQ / GBM);   // (48, 32)
    igates_gemm<<<ggrid, 256>>>(xs, Wi, bi);

    const size_t smem = (size_t)(H + CACHED * H + NROWS) * sizeof(float); // ~200 KB
    cudaFuncSetAttribute(gru_recur, cudaFuncAttributeMaxDynamicSharedMemorySize,
                         (int)smem);
    gru_recur<<<NCTA, RTH, smem>>>(init_state, Wh, bn, out);
}

// round 2
// speedup vs baseline: 1.3046x; 1.3046x over previous
#include <cuda_runtime.h>
#include <cuda_fp16.h>
#include <cstdint>
#include <math.h>

#define SEQ 4096
#define H 2048
#define IN_DIM 2048
#define G3 6144

// ---------------- scratch ---------------------------------------------------
__device__ float g_igates[(size_t)SEQ * G3];   // ~100.7 MB
__device__ unsigned int g_bar;

__global__ void init_bar_kernel() { g_bar = 0u; }

// ---------------- Kernel 1: igates = xs @ Wi^T + bi ------------------------
#define GBM 128
#define GBN 128
#define GBK 16

__global__ __launch_bounds__(256) void igates_gemm(
    const float* __restrict__ A,
    const float* __restrict__ B,
    const float* __restrict__ bias)
{
    __shared__ float As[GBK][GBM + 1];
    __shared__ float Bs[GBK][GBN + 1];

    const int bm = blockIdx.y * GBM;
    const int bn = blockIdx.x * GBN;
    const int tid = threadIdx.x;
    const int tx = tid & 15;
    const int ty = tid >> 4;
    const int lr = tid >> 2;
    const int lc = tid & 3;

    float acc[8][8];
    #pragma unroll
    for (int i = 0; i < 8; i++)
        #pragma unroll
        for (int j = 0; j < 8; j++) acc[i][j] = 0.f;

    for (int k0 = 0; k0 < IN_DIM; k0 += GBK) {
        #pragma unroll
        for (int s = 0; s < 2; s++) {
            const int row = lr + 64 * s;
            float4 va = *(const float4*)(A + (size_t)(bm + row) * IN_DIM + k0 + 4 * lc);
            As[4*lc+0][row] = va.x; As[4*lc+1][row] = va.y;
            As[4*lc+2][row] = va.z; As[4*lc+3][row] = va.w;
            float4 vb = *(const float4*)(B + (size_t)(bn + row) * IN_DIM + k0 + 4 * lc);
            Bs[4*lc+0][row] = vb.x; Bs[4*lc+1][row] = vb.y;
            Bs[4*lc+2][row] = vb.z; Bs[4*lc+3][row] = vb.w;
        }
        __syncthreads();

        #pragma unroll
        for (int k = 0; k < GBK; k++) {
            float a[8], b[8];
            #pragma unroll
            for (int i = 0; i < 8; i++) a[i] = As[k][ty * 8 + i];
            #pragma unroll
            for (int j = 0; j < 8; j++) b[j] = Bs[k][tx * 8 + j];
            #pragma unroll
            for (int i = 0; i < 8; i++)
                #pragma unroll
                for (int j = 0; j < 8; j++) acc[i][j] += a[i] * b[j];
        }
        __syncthreads();
    }

    #pragma unroll
    for (int i = 0; i < 8; i++) {
        const int row = bm + ty * 8 + i;
        const int col = bn + tx * 8;
        float4 o0, o1;
        o0.x = acc[i][0] + bias[col + 0];
        o0.y = acc[i][1] + bias[col + 1];
        o0.z = acc[i][2] + bias[col + 2];
        o0.w = acc[i][3] + bias[col + 3];
        o1.x = acc[i][4] + bias[col + 4];
        o1.y = acc[i][5] + bias[col + 5];
        o1.z = acc[i][6] + bias[col + 6];
        o1.w = acc[i][7] + bias[col + 7];
        float* cp = g_igates + (size_t)row * G3 + col;
        *(float4*)(cp + 0) = o0;
        *(float4*)(cp + 4) = o1;
    }
}

// ---------------- Kernel 2: persistent GRU recurrence ----------------------
// 128 CTAs (1/SM). Each owns 16 hidden indices => 48 Wh rows, ALL cached in
// SMEM as fp16 (192 KB). fp32 h and fp32 accumulation. One grid barrier/step.
#define NCTA 128
#define PER 16
#define NROWS 48
#define RTH 256

__global__ __launch_bounds__(RTH, 1) void gru_recur(
    const float* __restrict__ init_state,
    const float* __restrict__ Wh,
    const float* __restrict__ bn,
    float* __restrict__ out)
{
    extern __shared__ float smem[];
    float*  h_s = smem;                                  // H floats (8 KB)
    __half* wc  = (__half*)(smem + H);                   // NROWS*H halves (192 KB)
    float*  red = (float*)(wc + (size_t)NROWS * H);      // NROWS floats

    const int tid  = threadIdx.x;
    const int lane = tid & 31;
    const int wid  = tid >> 5;
    const int base = blockIdx.x * PER;

    // prologue: convert+cache this CTA's 48 Wh rows into SMEM (fp16)
    for (int r = 0; r < NROWS; r++) {
        const int gate = r >> 4, i = r & 15;
        const float4* src = (const float4*)(Wh + (size_t)(gate * H + base + i) * H);
        __half2* dst = (__half2*)(wc + (size_t)r * H);
        for (int v = tid; v < H / 4; v += RTH) {
            float4 w = src[v];
            dst[2 * v + 0] = __floats2half2_rn(w.x, w.y);
            dst[2 * v + 1] = __floats2half2_rn(w.z, w.w);
        }
    }

    float bnv = 0.f, lastv = 0.f;
    if (tid < PER) bnv = bn[base + tid];

    for (int t = 0; t < SEQ; t++) {
        // ---- load h_{t-1} into SMEM ----
        const float4* hsrc = (t == 0) ? (const float4*)init_state
                                      : (const float4*)(out + (size_t)(t - 1) * H);
        for (int v = tid; v < H / 4; v += RTH)
            ((float4*)h_s)[v] = __ldcg(hsrc + v);
        __syncthreads();

        // ---- 48 dot products: warp per row, 6 rows per warp ----
        for (int rr = wid; rr < NROWS; rr += RTH / 32) {
            const uint4* wp = (const uint4*)(wc + (size_t)rr * H);  // 8 halves/lane/iter
            const float4* hp = (const float4*)h_s;
            float s0 = 0.f, s1 = 0.f, s2 = 0.f, s3 = 0.f;
            #pragma unroll
            for (int j = 0; j < 8; j++) {           // 8 iters * 8 halves = 64/lane
                uint4 w4 = wp[j * 32 + lane];
                __half2 a0 = *(__half2*)&w4.x;
                __half2 a1 = *(__half2*)&w4.y;
                __half2 a2 = *(__half2*)&w4.z;
                __half2 a3 = *(__half2*)&w4.w;
                float4 h0 = hp[j * 64 + lane * 2 + 0];
                float4 h1 = hp[j * 64 + lane * 2 + 1];
                float2 f0 = __half22float2(a0);
                float2 f1 = __half22float2(a1);
                float2 f2 = __half22float2(a2);
                float2 f3 = __half22float2(a3);
                s0 = fmaf(f0.x, h0.x, s0); s1 = fmaf(f0.y, h0.y, s1);
                s2 = fmaf(f1.x, h0.z, s2); s3 = fmaf(f1.y, h0.w, s3);
                s0 = fmaf(f2.x, h1.x, s0); s1 = fmaf(f2.y, h1.y, s1);
                s2 = fmaf(f3.x, h1.z, s2); s3 = fmaf(f3.y, h1.w, s3);
            }
            float s = (s0 + s1) + (s2 + s3);
            #pragma unroll
            for (int o = 16; o; o >>= 1) s += __shfl_xor_sync(0xffffffffu, s, o);
            if (lane == 0) red[rr] = s;
        }
        __syncthreads();

        // ---- gate math + write h_t ----
        if (tid < PER) {
            const int idx = base + tid;
            const float hr = red[tid], hz = red[PER + tid], hn = red[2 * PER + tid];
            const float* ig = g_igates + (size_t)t * G3;
            const float gr = ig[idx], gz = ig[H + idx], gn = ig[2 * H + idx];
            const float reset  = 1.f / (1.f + expf(-(gr + hr)));
            const float update = 1.f / (1.f + expf(-(gz + hz)));
            const float nv = tanhf(gn + reset * (hn + bnv));
            const float hp = h_s[idx];
            const float hnext = (1.f - update) * nv + update * hp;
            __stcg(out + (size_t)t * H + idx, hnext);
            lastv = hnext;
        }
        __threadfence();
        __syncthreads();

        // ---- grid barrier ----
        if (tid == 0) {
            atomicAdd(&g_bar, 1u);
            const unsigned target = (unsigned)(t + 1) * NCTA;
            while (*((volatile unsigned int*)&g_bar) < target) { }
            __threadfence();
        }
        __syncthreads();
    }

    if (tid < PER) out[(size_t)SEQ * H + base + tid] = lastv;
}

// ---------------- launch -----------------------------------------------------
extern "C" void kernel_launch(void* const* d_in, const int* in_sizes, int n_in,
                              void* d_out, int out_size)
{
    const float* xs         = (const float*)d_in[0];
    const float* init_state = (const float*)d_in[1];
    const float* Wi         = (const float*)d_in[2];
    const float* Wh         = (const float*)d_in[3];
    const float* bi         = (const float*)d_in[4];
    const float* bn         = (const float*)d_in[5];
    float* out = (float*)d_out;

    init_bar_kernel<<<1, 1>>>();

    dim3 ggrid(G3 / GBN, SEQ / GBM);
    igates_gemm<<<ggrid, 256>>>(xs, Wi, bi);

    const size_t smem = (size_t)H * sizeof(float)
                      + (size_t)NROWS * H * sizeof(__half)
                      + NROWS * sizeof(float);            // ~205 KB
    cudaFuncSetAttribute(gru_recur, cudaFuncAttributeMaxDynamicSharedMemorySize,
                         (int)smem);
    gru_recur<<<NCTA, RTH, smem>>>(init_state, Wh, bn, out);
}